// round 1
// baseline (speedup 1.0000x reference)
#include <cuda_runtime.h>
#include <stdint.h>

#define NN 200000
#define EE 3200000
#define EPSF 1e-5f

// ---------------- scratch (static device globals; no runtime allocation) ----
__device__ float  g_deg[NN];          // degree -> dis (in place)
__device__ float  g_wn [EE];          // normalized edge weights
__device__ float  g_xn [NN * 64];     // normalized layer input (Tx0)
__device__ float  g_t1 [NN * 64];     // Tx1 = spmm(Tx0)
__device__ float  g_t2 [NN * 64];     // spmm(Tx1)
__device__ float  g_x1 [NN * 4];
__device__ float  g_x2 [NN * 16];
__device__ float  g_x3 [NN * 64];
__device__ float  g_x4 [NN * 1];
__device__ double g_stats[128];       // [0:64) sum, [64:128) sumsq

// ---------------- buffer selectors (device side, so host never needs symbols)
__device__ __forceinline__ const float* in_sel(int id, const float* x0) {
    switch (id) {
        case 0: return x0;
        case 1: return g_x1;
        case 2: return g_x2;
        case 3: return g_x3;
    }
    return x0;
}
__device__ __forceinline__ float* out_sel(int id) {
    switch (id) {
        case 1: return g_x1;
        case 2: return g_x2;
        case 3: return g_x3;
    }
    return g_x4;
}

// ---------------- small utility kernels --------------------------------------
__global__ void k_zero(int which, int count) {
    int i = blockIdx.x * blockDim.x + threadIdx.x;
    if (i >= count) return;
    float* p = (which == 0) ? g_t1 : (which == 1) ? g_t2 : g_deg;
    p[i] = 0.f;
}

__global__ void k_zero_stats() {
    int i = threadIdx.x;
    if (i < 128) g_stats[i] = 0.0;
}

__global__ void k_deg(const int* __restrict__ row, const float* __restrict__ w, int E) {
    int e = blockIdx.x * blockDim.x + threadIdx.x;
    if (e < E) atomicAdd(&g_deg[row[e]], w[e]);
}

__global__ void k_dis(int n) {
    int i = blockIdx.x * blockDim.x + threadIdx.x;
    if (i < n) {
        float d = g_deg[i];
        g_deg[i] = (d > 0.f) ? rsqrtf(d) : 0.f;
    }
}

__global__ void k_wn(const int* __restrict__ row, const int* __restrict__ col,
                     const float* __restrict__ w, int E) {
    int e = blockIdx.x * blockDim.x + threadIdx.x;
    if (e < E) g_wn[e] = -g_deg[row[e]] * w[e] * g_deg[col[e]];
}

// ---------------- instance-norm: reduce + normalize --------------------------
template <int F>
__global__ void k_reduce(const float* __restrict__ x0, int id, int n) {
    const float* x = in_sel(id, x0);
    __shared__ double ss[256], sq[256];
    int tid = threadIdx.x;
    double s = 0.0, q = 0.0;
    int total = n * F;
    for (int idx = blockIdx.x * 256 + tid; idx < total; idx += gridDim.x * 256) {
        float v = x[idx];
        s += (double)v;
        q += (double)v * (double)v;
    }
    ss[tid] = s; sq[tid] = q;
    __syncthreads();
    // 256 % F == 0 and stride % F == 0, so channel(tid) = tid & (F-1) is invariant
    for (int st = 128; st >= F; st >>= 1) {
        if (tid < st) { ss[tid] += ss[tid + st]; sq[tid] += sq[tid + st]; }
        __syncthreads();
    }
    if (tid < F) {
        atomicAdd(&g_stats[tid], ss[tid]);
        atomicAdd(&g_stats[64 + tid], sq[tid]);
    }
}

template <int F>
__global__ void k_norm(const float* __restrict__ x0, int id, int n) {
    const float* x = in_sel(id, x0);
    int idx = blockIdx.x * blockDim.x + threadIdx.x;
    int total = n * F;
    if (idx >= total) return;
    int c = idx & (F - 1);
    double inv_n = 1.0 / (double)n;
    double m = g_stats[c] * inv_n;
    double v = g_stats[64 + c] * inv_n - m * m;
    float r = rsqrtf((float)v + EPSF);
    g_xn[idx] = (float)((double)x[idx] - m) * r;
}

// ---------------- SpMM scatter: out[col] += wn * in[row] ---------------------
// src==0: g_xn -> g_t1 ; src==1: g_t1 -> g_t2
template <int F>
__global__ void k_spmm(const int* __restrict__ row, const int* __restrict__ col,
                       int src, int E) {
    const float* __restrict__ xin = (src == 0) ? g_xn : g_t1;
    float* __restrict__ out       = (src == 0) ? g_t1 : g_t2;
    if constexpr (F >= 4) {
        constexpr int G = F / 4;              // float4 groups per edge
        int idx = blockIdx.x * blockDim.x + threadIdx.x;
        if (idx >= E * G) return;
        int e = idx / G;
        int g = idx - e * G;
        float w = g_wn[e];
        const float4 xv = *(const float4*)(xin + (size_t)row[e] * F + g * 4);
        float* o = out + (size_t)col[e] * F + g * 4;
        atomicAdd(o + 0, w * xv.x);
        atomicAdd(o + 1, w * xv.y);
        atomicAdd(o + 2, w * xv.z);
        atomicAdd(o + 3, w * xv.w);
    } else {
        int e = blockIdx.x * blockDim.x + threadIdx.x;
        if (e >= E) return;
        atomicAdd(&out[col[e]], g_wn[e] * xin[row[e]]);
    }
}

// ---------------- Cheb combine: relu(Tx0@W0 + Tx1@W1 + (2*t2-Tx0)@W2 + b) ----
template <int F, int FO>
__global__ void k_combine(const float* __restrict__ W, const float* __restrict__ b,
                          int outid, int n) {
    int idx = blockIdx.x * blockDim.x + threadIdx.x;
    if (idx >= n * FO) return;
    int node = idx / FO;
    int co   = idx - node * FO;
    float* out = out_sel(outid);
    const float* xr = g_xn + (size_t)node * F;
    const float* t1 = g_t1 + (size_t)node * F;
    const float* t2 = g_t2 + (size_t)node * F;
    float acc = __ldg(b + co);
#pragma unroll
    for (int i = 0; i < F; i++) {
        float x0 = xr[i];
        float x1 = t1[i];
        float x2 = 2.f * t2[i] - x0;
        acc += x0 * __ldg(W + i * FO + co)
             + x1 * __ldg(W + (F + i) * FO + co)
             + x2 * __ldg(W + (2 * F + i) * FO + co);
    }
    out[idx] = fmaxf(acc, 0.f);
}

// ---------------- node MLP: 85 -> 40 -> 16 -> 1 (weights staged in shared) ---
__global__ __launch_bounds__(128) void k_nodemlp(
    const float* __restrict__ W1, const float* __restrict__ B1,
    const float* __restrict__ W2, const float* __restrict__ B2,
    const float* __restrict__ W3, const float* __restrict__ B3,
    float* __restrict__ out, int n) {
    __shared__ float sW1[85 * 40];
    __shared__ float sB1[40];
    __shared__ float sW2[40 * 16];
    __shared__ float sB2[16];
    __shared__ float sW3[16];
    __shared__ float sB3[1];
    for (int i = threadIdx.x; i < 85 * 40; i += blockDim.x) sW1[i] = W1[i];
    for (int i = threadIdx.x; i < 40;      i += blockDim.x) sB1[i] = B1[i];
    for (int i = threadIdx.x; i < 40 * 16; i += blockDim.x) sW2[i] = W2[i];
    for (int i = threadIdx.x; i < 16;      i += blockDim.x) sB2[i] = B2[i];
    for (int i = threadIdx.x; i < 16;      i += blockDim.x) sW3[i] = W3[i];
    if (threadIdx.x == 0) sB3[0] = B3[0];
    __syncthreads();

    int node = blockIdx.x * blockDim.x + threadIdx.x;
    if (node >= n) return;

    float h1[40];
#pragma unroll
    for (int j = 0; j < 40; j++) h1[j] = sB1[j];

#pragma unroll
    for (int i = 0; i < 4; i++) {
        float xi = g_x1[(size_t)node * 4 + i];
#pragma unroll
        for (int j = 0; j < 40; j++) h1[j] += xi * sW1[i * 40 + j];
    }
#pragma unroll 1
    for (int i = 0; i < 16; i++) {
        float xi = g_x2[(size_t)node * 16 + i];
#pragma unroll
        for (int j = 0; j < 40; j++) h1[j] += xi * sW1[(4 + i) * 40 + j];
    }
#pragma unroll 1
    for (int i = 0; i < 64; i++) {
        float xi = g_x3[(size_t)node * 64 + i];
#pragma unroll
        for (int j = 0; j < 40; j++) h1[j] += xi * sW1[(20 + i) * 40 + j];
    }
    {
        float xi = g_x4[node];
#pragma unroll
        for (int j = 0; j < 40; j++) h1[j] += xi * sW1[84 * 40 + j];
    }

    float h2[16];
#pragma unroll
    for (int j = 0; j < 16; j++) h2[j] = sB2[j];
#pragma unroll 1
    for (int i = 0; i < 40; i++) {
        float v = fmaxf(h1[i], 0.f);
#pragma unroll
        for (int j = 0; j < 16; j++) h2[j] += v * sW2[i * 16 + j];
    }
    float o = sB3[0];
#pragma unroll
    for (int i = 0; i < 16; i++) o += fmaxf(h2[i], 0.f) * sW3[i];
    out[node] = fmaxf(o, 0.f);
}

// ---------------- fused two-stage edge MLP -----------------------------------
__device__ __forceinline__ float edge_block(
    float s, float d, float a,
    const float* __restrict__ w1, const float* __restrict__ b1,
    const float* __restrict__ g,  const float* __restrict__ be,
    const float* __restrict__ w2, const float* __restrict__ b2) {
    // h = relu([s,d,a] @ w1 + b1), layernorm over 2, @ w2 + b2
    float h0 = s * w1[0] + d * w1[2] + a * w1[4] + b1[0];
    float h1 = s * w1[1] + d * w1[3] + a * w1[5] + b1[1];
    h0 = fmaxf(h0, 0.f);
    h1 = fmaxf(h1, 0.f);
    float m  = 0.5f * (h0 + h1);
    float d0 = h0 - m, d1 = h1 - m;
    float v  = 0.5f * (d0 * d0 + d1 * d1);
    float r  = rsqrtf(v + EPSF);
    float n0 = d0 * r * g[0] + be[0];
    float n1 = d1 * r * g[1] + be[1];
    return n0 * w2[0] + n1 * w2[1] + b2[0];
}

__global__ void k_edgemlp(
    const int* __restrict__ row, const int* __restrict__ col,
    const float* __restrict__ eattr, const float* __restrict__ xo,
    const float* __restrict__ w1a, const float* __restrict__ b1a,
    const float* __restrict__ ga,  const float* __restrict__ bea,
    const float* __restrict__ w2a, const float* __restrict__ b2a,
    const float* __restrict__ w1b, const float* __restrict__ b1b,
    const float* __restrict__ gb,  const float* __restrict__ beb,
    const float* __restrict__ w2b, const float* __restrict__ b2b,
    float* __restrict__ out, int E) {
    int e = blockIdx.x * blockDim.x + threadIdx.x;
    if (e >= E) return;
    float s = xo[row[e]];
    float d = xo[col[e]];
    float a = eattr[e];
    float a1 = fmaxf(edge_block(s, d, a,  w1a, b1a, ga, bea, w2a, b2a), 0.f);
    float a2 = fmaxf(edge_block(s, d, a1, w1b, b1b, gb, beb, w2b, b2b), 0.f);
    out[e] = a2;
}

// ---------------- host orchestration ----------------------------------------
static inline int cdiv(int a, int b) { return (a + b - 1) / b; }

template <int F, int FO>
static void run_layer(const float* xin, int inid, const float* W, const float* b,
                      int outid, const int* row, const int* col, int n, int E) {
    const int B = 256;
    int nf = n * F;
    k_zero_stats<<<1, 128>>>();
    {
        int grid = cdiv(nf, 256);
        if (grid > 2048) grid = 2048;
        k_reduce<F><<<grid, 256>>>(xin, inid, n);
    }
    k_norm<F><<<cdiv(nf, B), B>>>(xin, inid, n);
    k_zero<<<cdiv(nf, B), B>>>(0, nf);
    if constexpr (F >= 4) {
        k_spmm<F><<<cdiv(E * (F / 4), B), B>>>(row, col, 0, E);
    } else {
        k_spmm<F><<<cdiv(E, B), B>>>(row, col, 0, E);
    }
    k_zero<<<cdiv(nf, B), B>>>(1, nf);
    if constexpr (F >= 4) {
        k_spmm<F><<<cdiv(E * (F / 4), B), B>>>(row, col, 1, E);
    } else {
        k_spmm<F><<<cdiv(E, B), B>>>(row, col, 1, E);
    }
    k_combine<F, FO><<<cdiv(n * FO, B), B>>>(W, b, outid, n);
}

extern "C" void kernel_launch(void* const* d_in, const int* in_sizes, int n_in,
                              void* d_out, int out_size) {
    const float* x     = (const float*)d_in[0];
    const int*   ei    = (const int*)  d_in[1];
    const float* eattr = (const float*)d_in[2];
    const float* c1W = (const float*)d_in[3],  *c1b = (const float*)d_in[4];
    const float* c2W = (const float*)d_in[5],  *c2b = (const float*)d_in[6];
    const float* c3W = (const float*)d_in[7],  *c3b = (const float*)d_in[8];
    const float* c4W = (const float*)d_in[9],  *c4b = (const float*)d_in[10];
    const float* l1W = (const float*)d_in[11], *l1b = (const float*)d_in[12];
    const float* l2W = (const float*)d_in[13], *l2b = (const float*)d_in[14];
    const float* l3W = (const float*)d_in[15], *l3b = (const float*)d_in[16];

    int n = in_sizes[0];
    int E = in_sizes[1] / 2;
    const int* row = ei;
    const int* col = ei + E;
    float* xo    = (float*)d_out;
    float* eaout = (float*)d_out + n;

    const int B = 256;

    // degree -> dis -> normalized edge weights
    k_zero<<<cdiv(n, B), B>>>(2, n);
    k_deg <<<cdiv(E, B), B>>>(row, eattr, E);
    k_dis <<<cdiv(n, B), B>>>(n);
    k_wn  <<<cdiv(E, B), B>>>(row, col, eattr, E);

    // 4 Cheb layers
    run_layer<1, 4>  (x,       0, c1W, c1b, 1, row, col, n, E);
    run_layer<4, 16> (nullptr, 1, c2W, c2b, 2, row, col, n, E);
    run_layer<16, 64>(nullptr, 2, c3W, c3b, 3, row, col, n, E);
    run_layer<64, 1> (nullptr, 3, c4W, c4b, 4, row, col, n, E);

    // node MLP -> xo (written straight into d_out)
    k_nodemlp<<<cdiv(n, 128), 128>>>(l1W, l1b, l2W, l2b, l3W, l3b, xo, n);

    // fused two-stage edge MLP -> ea
    k_edgemlp<<<cdiv(E, B), B>>>(
        row, col, eattr, xo,
        (const float*)d_in[17], (const float*)d_in[18], (const float*)d_in[19],
        (const float*)d_in[20], (const float*)d_in[21], (const float*)d_in[22],
        (const float*)d_in[23], (const float*)d_in[24], (const float*)d_in[25],
        (const float*)d_in[26], (const float*)d_in[27], (const float*)d_in[28],
        eaout, E);
}

// round 2
// speedup vs baseline: 1.9684x; 1.9684x over previous
#include <cuda_runtime.h>
#include <stdint.h>

#define NN 200000
#define EE 3200000
#define EPSF 1e-5f
#define SCAN_B 1024

// ---------------- scratch (static device globals; no runtime allocation) ----
__device__ float  g_deg [NN];          // weighted degree -> dis (in place)
__device__ float  g_wn  [EE];          // normalized edge weights
__device__ int    g_degi[NN];          // int in-degree histogram (by col)
__device__ int    g_off [NN + 1];      // CSR offsets (by col)
__device__ int    g_cur [NN];          // fill cursors
__device__ int2   g_csr [EE];          // packed (row, w-as-int) sorted by col
__device__ int    g_bsum[1024];        // scan block sums
__device__ float  g_xn [NN * 64];      // normalized layer input (Tx0)
__device__ float  g_t1 [NN * 64];      // Tx1
__device__ float  g_t2 [NN * 64];      // spmm(Tx1)
__device__ float  g_x1 [NN * 4];
__device__ float  g_x2 [NN * 16];
__device__ float  g_x3 [NN * 64];
__device__ float  g_x4 [NN * 1];
__device__ double g_stats[128];        // [0:64) sum, [64:128) sumsq

// ---------------- buffer selectors ------------------------------------------
__device__ __forceinline__ const float* in_sel(int id, const float* x0) {
    switch (id) {
        case 0: return x0;
        case 1: return g_x1;
        case 2: return g_x2;
        case 3: return g_x3;
    }
    return x0;
}
__device__ __forceinline__ float* out_sel(int id) {
    switch (id) {
        case 1: return g_x1;
        case 2: return g_x2;
        case 3: return g_x3;
    }
    return g_x4;
}

// ---------------- small utility kernels --------------------------------------
__global__ void k_zerof(int n) {          // zero g_deg
    int i = blockIdx.x * blockDim.x + threadIdx.x;
    if (i < n) g_deg[i] = 0.f;
}
__global__ void k_zeroi(int n) {          // zero g_degi
    int i = blockIdx.x * blockDim.x + threadIdx.x;
    if (i < n) g_degi[i] = 0;
}
__global__ void k_zero_stats() {
    int i = threadIdx.x;
    if (i < 128) g_stats[i] = 0.0;
}

__global__ void k_deg(const int* __restrict__ row, const float* __restrict__ w, int E) {
    int e = blockIdx.x * blockDim.x + threadIdx.x;
    if (e < E) atomicAdd(&g_deg[row[e]], w[e]);
}

__global__ void k_dis(int n) {
    int i = blockIdx.x * blockDim.x + threadIdx.x;
    if (i < n) {
        float d = g_deg[i];
        g_deg[i] = (d > 0.f) ? rsqrtf(d) : 0.f;
    }
}

__global__ void k_wn(const int* __restrict__ row, const int* __restrict__ col,
                     const float* __restrict__ w, int E) {
    int e = blockIdx.x * blockDim.x + threadIdx.x;
    if (e < E) g_wn[e] = -g_deg[row[e]] * w[e] * g_deg[col[e]];
}

// ---------------- CSR build (by col) ----------------------------------------
__global__ void k_hist(const int* __restrict__ col, int E) {
    int e = blockIdx.x * blockDim.x + threadIdx.x;
    if (e < E) atomicAdd(&g_degi[col[e]], 1);
}

// block totals over padded domain [0, n+1)
__global__ void k_blocksum(int np) {
    __shared__ int sh[SCAN_B];
    int i = blockIdx.x * SCAN_B + threadIdx.x;
    sh[threadIdx.x] = (i < np - 1) ? g_degi[i] : 0;   // np = n+1; last elem is pad
    __syncthreads();
    for (int st = SCAN_B / 2; st > 0; st >>= 1) {
        if (threadIdx.x < st) sh[threadIdx.x] += sh[threadIdx.x + st];
        __syncthreads();
    }
    if (threadIdx.x == 0) g_bsum[blockIdx.x] = sh[0];
}

// exclusive scan of block sums (single block, nb <= 256)
__global__ void k_scanb(int nb) {
    __shared__ int sh[256];
    int t = threadIdx.x;
    int v = (t < nb) ? g_bsum[t] : 0;
    sh[t] = v;
    __syncthreads();
    for (int off = 1; off < 256; off <<= 1) {
        int a = (t >= off) ? sh[t - off] : 0;
        __syncthreads();
        sh[t] += a;
        __syncthreads();
    }
    if (t < nb) g_bsum[t] = sh[t] - v;  // exclusive
}

// write offsets: off[i] = blockbase + exclusive-scan-within-block; cursor copy
__global__ void k_offsets(int np) {
    __shared__ int sh[SCAN_B];
    int i = blockIdx.x * SCAN_B + threadIdx.x;
    int v = (i < np - 1) ? g_degi[i] : 0;
    sh[threadIdx.x] = v;
    __syncthreads();
    for (int off = 1; off < SCAN_B; off <<= 1) {
        int a = (threadIdx.x >= off) ? sh[threadIdx.x - off] : 0;
        __syncthreads();
        sh[threadIdx.x] += a;
        __syncthreads();
    }
    if (i < np) {
        int o = g_bsum[blockIdx.x] + sh[threadIdx.x] - v;
        g_off[i] = o;
        if (i < np - 1) g_cur[i] = o;
    }
}

__global__ void k_fill(const int* __restrict__ row, const int* __restrict__ col, int E) {
    int e = blockIdx.x * blockDim.x + threadIdx.x;
    if (e >= E) return;
    int c = col[e];
    int pos = atomicAdd(&g_cur[c], 1);
    g_csr[pos] = make_int2(row[e], __float_as_int(g_wn[e]));
}

// ---------------- instance-norm: reduce + normalize --------------------------
template <int F>
__global__ void k_reduce(const float* __restrict__ x0, int id, int n) {
    const float* x = in_sel(id, x0);
    __shared__ double ss[256], sq[256];
    int tid = threadIdx.x;
    double s = 0.0, q = 0.0;
    int total = n * F;
    for (int idx = blockIdx.x * 256 + tid; idx < total; idx += gridDim.x * 256) {
        float v = x[idx];
        s += (double)v;
        q += (double)v * (double)v;
    }
    ss[tid] = s; sq[tid] = q;
    __syncthreads();
    for (int st = 128; st >= F; st >>= 1) {
        if (tid < st) { ss[tid] += ss[tid + st]; sq[tid] += sq[tid + st]; }
        __syncthreads();
    }
    if (tid < F) {
        atomicAdd(&g_stats[tid], ss[tid]);
        atomicAdd(&g_stats[64 + tid], sq[tid]);
    }
}

template <int F>
__global__ void k_norm(const float* __restrict__ x0, int id, int n) {
    const float* x = in_sel(id, x0);
    int idx = blockIdx.x * blockDim.x + threadIdx.x;
    int total = n * F;
    if (idx >= total) return;
    int c = idx & (F - 1);
    double inv_n = 1.0 / (double)n;
    double m = g_stats[c] * inv_n;
    double v = g_stats[64 + c] * inv_n - m * m;
    float r = rsqrtf((float)v + EPSF);
    g_xn[idx] = (float)((double)x[idx] - m) * r;
}

// ---------------- gather SpMM: out[i] = sum_{j in csr[i]} w_j * xin[row_j] ---
// src==0: g_xn -> g_t1 ; src==1: g_t1 -> g_t2
template <int F>
__global__ void k_gspmm(int src, int n) {
    const float* __restrict__ xin = (src == 0) ? g_xn : g_t1;
    float* __restrict__ out       = (src == 0) ? g_t1 : g_t2;
    int gt = blockIdx.x * blockDim.x + threadIdx.x;

    if constexpr (F == 64) {
        int node = gt >> 5;
        int lane = threadIdx.x & 31;
        if (node >= n) return;
        int s = g_off[node], e = g_off[node + 1];
        float2 acc = make_float2(0.f, 0.f);
        for (int j = s; j < e; j++) {
            int2 rw = g_csr[j];                    // broadcast across warp
            float w = __int_as_float(rw.y);
            float2 xv = *(const float2*)(xin + (size_t)rw.x * 64 + lane * 2);
            acc.x += w * xv.x;
            acc.y += w * xv.y;
        }
        *(float2*)(out + (size_t)node * 64 + lane * 2) = acc;
    } else if constexpr (F == 16) {
        int node = gt >> 4;
        int lane = threadIdx.x & 15;
        if (node >= n) return;
        int s = g_off[node], e = g_off[node + 1];
        float acc = 0.f;
        for (int j = s; j < e; j++) {
            int2 rw = g_csr[j];
            acc += __int_as_float(rw.y) * xin[(size_t)rw.x * 16 + lane];
        }
        out[(size_t)node * 16 + lane] = acc;
    } else if constexpr (F == 4) {
        int node = gt;
        if (node >= n) return;
        int s = g_off[node], e = g_off[node + 1];
        float4 acc = make_float4(0.f, 0.f, 0.f, 0.f);
        for (int j = s; j < e; j++) {
            int2 rw = g_csr[j];
            float w = __int_as_float(rw.y);
            float4 xv = *(const float4*)(xin + (size_t)rw.x * 4);
            acc.x += w * xv.x; acc.y += w * xv.y;
            acc.z += w * xv.z; acc.w += w * xv.w;
        }
        *(float4*)(out + (size_t)node * 4) = acc;
    } else {  // F == 1
        int node = gt;
        if (node >= n) return;
        int s = g_off[node], e = g_off[node + 1];
        float acc = 0.f;
        for (int j = s; j < e; j++) {
            int2 rw = g_csr[j];
            acc += __int_as_float(rw.y) * xin[rw.x];
        }
        out[node] = acc;
    }
}

// ---------------- Cheb combine: relu(Tx0@W0 + Tx1@W1 + (2*t2-Tx0)@W2 + b) ----
template <int F, int FO>
__global__ void k_combine(const float* __restrict__ W, const float* __restrict__ b,
                          int outid, int n) {
    int idx = blockIdx.x * blockDim.x + threadIdx.x;
    if (idx >= n * FO) return;
    int node = idx / FO;
    int co   = idx - node * FO;
    float* out = out_sel(outid);
    const float* xr = g_xn + (size_t)node * F;
    const float* t1 = g_t1 + (size_t)node * F;
    const float* t2 = g_t2 + (size_t)node * F;
    float acc = __ldg(b + co);
#pragma unroll
    for (int i = 0; i < F; i++) {
        float x0 = xr[i];
        float x1 = t1[i];
        float x2 = 2.f * t2[i] - x0;
        acc += x0 * __ldg(W + i * FO + co)
             + x1 * __ldg(W + (F + i) * FO + co)
             + x2 * __ldg(W + (2 * F + i) * FO + co);
    }
    out[idx] = fmaxf(acc, 0.f);
}

// ---------------- node MLP: 85 -> 40 -> 16 -> 1 ------------------------------
__global__ __launch_bounds__(128) void k_nodemlp(
    const float* __restrict__ W1, const float* __restrict__ B1,
    const float* __restrict__ W2, const float* __restrict__ B2,
    const float* __restrict__ W3, const float* __restrict__ B3,
    float* __restrict__ out, int n) {
    __shared__ float sW1[85 * 40];
    __shared__ float sB1[40];
    __shared__ float sW2[40 * 16];
    __shared__ float sB2[16];
    __shared__ float sW3[16];
    __shared__ float sB3[1];
    for (int i = threadIdx.x; i < 85 * 40; i += blockDim.x) sW1[i] = W1[i];
    for (int i = threadIdx.x; i < 40;      i += blockDim.x) sB1[i] = B1[i];
    for (int i = threadIdx.x; i < 40 * 16; i += blockDim.x) sW2[i] = W2[i];
    for (int i = threadIdx.x; i < 16;      i += blockDim.x) sB2[i] = B2[i];
    for (int i = threadIdx.x; i < 16;      i += blockDim.x) sW3[i] = W3[i];
    if (threadIdx.x == 0) sB3[0] = B3[0];
    __syncthreads();

    int node = blockIdx.x * blockDim.x + threadIdx.x;
    if (node >= n) return;

    float h1[40];
#pragma unroll
    for (int j = 0; j < 40; j++) h1[j] = sB1[j];

#pragma unroll
    for (int i = 0; i < 4; i++) {
        float xi = g_x1[(size_t)node * 4 + i];
#pragma unroll
        for (int j = 0; j < 40; j++) h1[j] += xi * sW1[i * 40 + j];
    }
#pragma unroll 1
    for (int i = 0; i < 16; i++) {
        float xi = g_x2[(size_t)node * 16 + i];
#pragma unroll
        for (int j = 0; j < 40; j++) h1[j] += xi * sW1[(4 + i) * 40 + j];
    }
#pragma unroll 1
    for (int i = 0; i < 64; i++) {
        float xi = g_x3[(size_t)node * 64 + i];
#pragma unroll
        for (int j = 0; j < 40; j++) h1[j] += xi * sW1[(20 + i) * 40 + j];
    }
    {
        float xi = g_x4[node];
#pragma unroll
        for (int j = 0; j < 40; j++) h1[j] += xi * sW1[84 * 40 + j];
    }

    float h2[16];
#pragma unroll
    for (int j = 0; j < 16; j++) h2[j] = sB2[j];
#pragma unroll 1
    for (int i = 0; i < 40; i++) {
        float v = fmaxf(h1[i], 0.f);
#pragma unroll
        for (int j = 0; j < 16; j++) h2[j] += v * sW2[i * 16 + j];
    }
    float o = sB3[0];
#pragma unroll
    for (int i = 0; i < 16; i++) o += fmaxf(h2[i], 0.f) * sW3[i];
    out[node] = fmaxf(o, 0.f);
}

// ---------------- fused two-stage edge MLP -----------------------------------
__device__ __forceinline__ float edge_block(
    float s, float d, float a,
    const float* __restrict__ w1, const float* __restrict__ b1,
    const float* __restrict__ g,  const float* __restrict__ be,
    const float* __restrict__ w2, const float* __restrict__ b2) {
    float h0 = s * w1[0] + d * w1[2] + a * w1[4] + b1[0];
    float h1 = s * w1[1] + d * w1[3] + a * w1[5] + b1[1];
    h0 = fmaxf(h0, 0.f);
    h1 = fmaxf(h1, 0.f);
    float m  = 0.5f * (h0 + h1);
    float d0 = h0 - m, d1 = h1 - m;
    float v  = 0.5f * (d0 * d0 + d1 * d1);
    float r  = rsqrtf(v + EPSF);
    float n0 = d0 * r * g[0] + be[0];
    float n1 = d1 * r * g[1] + be[1];
    return n0 * w2[0] + n1 * w2[1] + b2[0];
}

__global__ void k_edgemlp(
    const int* __restrict__ row, const int* __restrict__ col,
    const float* __restrict__ eattr, const float* __restrict__ xo,
    const float* __restrict__ w1a, const float* __restrict__ b1a,
    const float* __restrict__ ga,  const float* __restrict__ bea,
    const float* __restrict__ w2a, const float* __restrict__ b2a,
    const float* __restrict__ w1b, const float* __restrict__ b1b,
    const float* __restrict__ gb,  const float* __restrict__ beb,
    const float* __restrict__ w2b, const float* __restrict__ b2b,
    float* __restrict__ out, int E) {
    int e = blockIdx.x * blockDim.x + threadIdx.x;
    if (e >= E) return;
    float s = xo[row[e]];
    float d = xo[col[e]];
    float a = eattr[e];
    float a1 = fmaxf(edge_block(s, d, a,  w1a, b1a, ga, bea, w2a, b2a), 0.f);
    float a2 = fmaxf(edge_block(s, d, a1, w1b, b1b, gb, beb, w2b, b2b), 0.f);
    out[e] = a2;
}

// ---------------- host orchestration ----------------------------------------
static inline int cdiv(int a, int b) { return (a + b - 1) / b; }

template <int F, int FO>
static void run_layer(const float* xin, int inid, const float* W, const float* b,
                      int outid, int n, int E) {
    const int B = 256;
    int nf = n * F;
    k_zero_stats<<<1, 128>>>();
    {
        int grid = cdiv(nf, 256);
        if (grid > 2048) grid = 2048;
        k_reduce<F><<<grid, 256>>>(xin, inid, n);
    }
    k_norm<F><<<cdiv(nf, B), B>>>(xin, inid, n);
    int threads = (F == 64) ? n * 32 : (F == 16) ? n * 16 : n;
    k_gspmm<F><<<cdiv(threads, B), B>>>(0, n);
    k_gspmm<F><<<cdiv(threads, B), B>>>(1, n);
    k_combine<F, FO><<<cdiv(n * FO, B), B>>>(W, b, outid, n);
}

extern "C" void kernel_launch(void* const* d_in, const int* in_sizes, int n_in,
                              void* d_out, int out_size) {
    const float* x     = (const float*)d_in[0];
    const int*   ei    = (const int*)  d_in[1];
    const float* eattr = (const float*)d_in[2];
    const float* c1W = (const float*)d_in[3],  *c1b = (const float*)d_in[4];
    const float* c2W = (const float*)d_in[5],  *c2b = (const float*)d_in[6];
    const float* c3W = (const float*)d_in[7],  *c3b = (const float*)d_in[8];
    const float* c4W = (const float*)d_in[9],  *c4b = (const float*)d_in[10];
    const float* l1W = (const float*)d_in[11], *l1b = (const float*)d_in[12];
    const float* l2W = (const float*)d_in[13], *l2b = (const float*)d_in[14];
    const float* l3W = (const float*)d_in[15], *l3b = (const float*)d_in[16];

    int n = in_sizes[0];
    int E = in_sizes[1] / 2;
    const int* row = ei;
    const int* col = ei + E;
    float* xo    = (float*)d_out;
    float* eaout = (float*)d_out + n;

    const int B = 256;

    // degree -> dis -> normalized edge weights
    k_zerof<<<cdiv(n, B), B>>>(n);
    k_deg  <<<cdiv(E, B), B>>>(row, eattr, E);
    k_dis  <<<cdiv(n, B), B>>>(n);
    k_wn   <<<cdiv(E, B), B>>>(row, col, eattr, E);

    // CSR build (by col)
    int np = n + 1;
    int nb = cdiv(np, SCAN_B);
    k_zeroi   <<<cdiv(n, B), B>>>(n);
    k_hist    <<<cdiv(E, B), B>>>(col, E);
    k_blocksum<<<nb, SCAN_B>>>(np);
    k_scanb   <<<1, 256>>>(nb);
    k_offsets <<<nb, SCAN_B>>>(np);
    k_fill    <<<cdiv(E, B), B>>>(row, col, E);

    // 4 Cheb layers (gather SpMM, no atomics)
    run_layer<1, 4>  (x,       0, c1W, c1b, 1, n, E);
    run_layer<4, 16> (nullptr, 1, c2W, c2b, 2, n, E);
    run_layer<16, 64>(nullptr, 2, c3W, c3b, 3, n, E);
    run_layer<64, 1> (nullptr, 3, c4W, c4b, 4, n, E);

    // node MLP -> xo
    k_nodemlp<<<cdiv(n, 128), 128>>>(l1W, l1b, l2W, l2b, l3W, l3b, xo, n);

    // fused two-stage edge MLP -> ea
    k_edgemlp<<<cdiv(E, B), B>>>(
        row, col, eattr, xo,
        (const float*)d_in[17], (const float*)d_in[18], (const float*)d_in[19],
        (const float*)d_in[20], (const float*)d_in[21], (const float*)d_in[22],
        (const float*)d_in[23], (const float*)d_in[24], (const float*)d_in[25],
        (const float*)d_in[26], (const float*)d_in[27], (const float*)d_in[28],
        eaout, E);
}